// round 10
// baseline (speedup 1.0000x reference)
#include <cuda_runtime.h>
#include <cstdint>

#define T_LEN  16384
#define BATCH  10
#define DDIM   3
#define HDIM   4
#define NITER  10
#define NCHAIN (NITER*BATCH)   // 100
#define NGATE  16

// ---------------- device scratch (static: no allocation allowed) ----------------
__device__ float g_W2[NITER*DDIM*NGATE];                // zx & 0.5-scale folded: [iter][d][k]
__device__ float g_U2[NITER*HDIM*NGATE];                // zh & 0.5-scale folded: [iter][j][k]
__device__ float g_xproj[(size_t)NCHAIN*T_LEN*NGATE];   // 104.9 MB  [chain][t][k]
__device__ float g_scratch[(size_t)T_LEN*NCHAIN*16];    // 104.9 MB  [t][chain][u][4] = (o,h,c,tc)
__device__ float g_dump[NGATE*4];                       // dump target for lanes 4-15

// ---------------- helpers ----------------
__device__ __forceinline__ float tanh_ap(float x) {
    float y; asm("tanh.approx.f32 %0, %1;" : "=f"(y) : "f"(x)); return y;
}

// ---------------- 1) fold masks/scales into W2, U2 ----------------
// gate order k = gate*4 + unit, gates: 0=i 1=f 2=o 3=g. Scale 0.5 for i,f,o
// (sigmoid(a) = 0.5*tanh(a/2)+0.5), 1.0 for g.
__global__ void setup_k(const float* __restrict__ zx, const float* __restrict__ zh,
                        const float* __restrict__ Wi, const float* __restrict__ Ui,
                        const float* __restrict__ Wf, const float* __restrict__ Uf,
                        const float* __restrict__ Wo, const float* __restrict__ Uo,
                        const float* __restrict__ Wg, const float* __restrict__ Ug) {
    int tid = blockIdx.x * blockDim.x + threadIdx.x;
    if (tid < NITER*DDIM*NGATE) {                  // W2: zx * W * scale
        int k = tid % NGATE, d = (tid / NGATE) % DDIM, it = tid / (NGATE*DDIM);
        int gate = k >> 2, u = k & 3;
        const float* W = (gate == 0) ? Wi : (gate == 1) ? Wf : (gate == 2) ? Wo : Wg;
        float s = (gate < 3) ? 0.5f : 1.0f;
        g_W2[tid] = zx[it*DDIM + d] * W[d*HDIM + u] * s;
    }
    if (tid < NITER*HDIM*NGATE) {                  // U2: zh * U * scale
        int k = tid % NGATE, j = (tid / NGATE) % HDIM, it = tid / (NGATE*HDIM);
        int gate = k >> 2, u = k & 3;
        const float* U = (gate == 0) ? Ui : (gate == 1) ? Uf : (gate == 2) ? Uo : Ug;
        float s = (gate < 3) ? 0.5f : 1.0f;
        g_U2[tid] = zh[it*HDIM + j] * U[j*HDIM + u] * s;
    }
}

// ---------------- 2) precompute xproj[chain][t][16] ----------------
__global__ void __launch_bounds__(256) xproj_k(const float* __restrict__ x) {
    int tid = blockIdx.x * blockDim.x + threadIdx.x;     // chain-major, t fastest
    int t = tid % T_LEN;
    int chain = tid / T_LEN;
    if (chain >= NCHAIN) return;
    int it = chain / BATCH, b = chain % BATCH;
    const float* xr = x + ((size_t)t*BATCH + b)*DDIM;
    float x0 = xr[0], x1 = xr[1], x2 = xr[2];
    const float* W = g_W2 + it*DDIM*NGATE;
    float v[NGATE];
#pragma unroll
    for (int k = 0; k < NGATE; k++)
        v[k] = x0*W[k] + x1*W[NGATE + k] + x2*W[2*NGATE + k];
    float4* out = (float4*)(g_xproj + ((size_t)chain*T_LEN + t)*NGATE);
    out[0] = make_float4(v[0],  v[1],  v[2],  v[3]);
    out[1] = make_float4(v[4],  v[5],  v[6],  v[7]);
    out[2] = make_float4(v[8],  v[9],  v[10], v[11]);
    out[3] = make_float4(v[12], v[13], v[14], v[15]);
}

// ---------------- 3) serial recurrence: 16 lanes per chain, gates on lanes ----------------
// lane k = gate*4 + unit; lanes 0-3 additionally own unit u (c,h state).
// Identical dataflow to the 1926us version; ONLY change: the store is now
// convergent (all lanes issue the same STG.128; lanes 4-15 target a fixed
// dump buffer via a base pointer selected once before the loop). This removes
// the per-step BSSY/BSYNC pair (~70 cyc/step).
__global__ void __launch_bounds__(16, 1) lstm_k() {
    const int lane  = threadIdx.x;      // 0..15
    const int chain = blockIdx.x;
    const int u = lane & 3;
    const unsigned FULL = 0xFFFFu;

    // per-lane U column (zh mask & sigmoid half-scale already folded)
    const float* Ub = g_U2 + (chain / BATCH)*HDIM*NGATE;
    const float u0 = Ub[0*NGATE + lane];
    const float u1 = Ub[1*NGATE + lane];
    const float u2 = Ub[2*NGATE + lane];
    const float u3 = Ub[3*NGATE + lane];

    const float* xp = g_xproj + (size_t)chain*T_LEN*NGATE + lane;

    // convergent store base: lanes 0-3 -> real scratch (stride NCHAIN*16 floats
    // per step), lanes 4-15 -> fixed dump slot (stride 0). Selected ONCE.
    float4* stp = (lane < 4)
        ? (float4*)(g_scratch + ((size_t)chain*4 + u)*4)
        : (float4*)g_dump + lane;
    const size_t sstep = (lane < 4) ? (size_t)(NCHAIN*16/4) : 0;  // float4 units/step

    float h = 0.f, c = 0.f;

    // 8-deep per-lane register prefetch pipeline for xproj (1 coalesced 64B LDG/step)
    float xbuf[8];
#pragma unroll
    for (int p = 0; p < 8; p++) xbuf[p] = xp[(size_t)p*NGATE];

    for (int t = 0; t < T_LEN; t += 8) {
#pragma unroll
        for (int p = 0; p < 8; p++) {
            float xv = xbuf[p];
            int nf = t + 8 + p; nf = (nf < T_LEN) ? nf : (T_LEN - 1);
            xbuf[p] = xp[(size_t)nf*NGATE];              // ~1000 cyc lookahead (issue-only cost, hidden)

            // broadcast h (lanes 0-3 own h_u)
            float h0 = __shfl_sync(FULL, h, 0, 16);
            float h1 = __shfl_sync(FULL, h, 1, 16);
            float h2 = __shfl_sync(FULL, h, 2, 16);
            float h3 = __shfl_sync(FULL, h, 3, 16);

            // gate pre-activation a_k = xp_k + sum_j h_j * U2[j][k]  (tree, depth 12)
            float pa = fmaf(h0, u0, xv);
            float pb = fmaf(h3, u3, h2*u2);
            pa = fmaf(h1, u1, pa);
            float a = pa + pb;

            float tv = tanh_ap(a);                       // 1 MUFU: all 16 gates

            // gather the other three gates for unit u
            float tf = __shfl_sync(FULL, tv,  4 + u, 16);
            float to = __shfl_sync(FULL, tv,  8 + u, 16);
            float tg = __shfl_sync(FULL, tv, 12 + u, 16);

            // sigmoid(x) = 0.5*tanh(x/2)+0.5 (the /2 is folded into W2/U2)
            float iv = fmaf(tv, 0.5f, 0.5f);             // lanes 0-3: own tv IS t_i[u]
            float fv = fmaf(tf, 0.5f, 0.5f);
            float ov = fmaf(to, 0.5f, 0.5f);

            c = fmaf(fv, c, iv*tg);
            float tc = tanh_ap(c);                       // 1 MUFU: 4 cells
            h = ov*tc;

            // convergent STG.128 every lane; only lanes 0-3 hit real scratch.
            // lanes 4-15 values are bounded (tanh/sigmoid outputs) and never read.
            stp[(size_t)(t + p)*sstep] = make_float4(ov, h, c, tc);
        }
    }
}

// ---------------- 4) deterministic mean over the 10 MC iterations ----------------
__global__ void __launch_bounds__(256) reduce_k(float* __restrict__ out) {
    int tid = blockIdx.x * blockDim.x + threadIdx.x;
    if (tid >= T_LEN*BATCH*HDIM) return;
    int u = tid & 3;
    int b = (tid >> 2) % BATCH;
    int t = tid / (BATCH*HDIM);
    const float4* base = (const float4*)g_scratch + (size_t)t*NCHAIN*4 + b*4 + u;
    float so = 0.f, sh = 0.f, scc = 0.f;
#pragma unroll
    for (int it = 0; it < NITER; it++) {
        float4 v = base[(size_t)it*BATCH*4];             // chain = it*BATCH + b
        so += v.x; sh += v.y; scc += v.z;
    }
    size_t o_idx = ((size_t)t*BATCH + b)*HDIM + u;
    const size_t TEN = (size_t)T_LEN*BATCH*HDIM;
    out[o_idx]         = 0.1f*so;
    out[TEN + o_idx]   = 0.1f*sh;
    out[2*TEN + o_idx] = 0.1f*scc;
}

// ---------------- launch ----------------
extern "C" void kernel_launch(void* const* d_in, const int* in_sizes, int n_in,
                              void* d_out, int out_size) {
    const float* input = (const float*)d_in[0];
    const float* zx    = (const float*)d_in[1];
    const float* zh    = (const float*)d_in[2];
    const float* Wi    = (const float*)d_in[3];
    const float* Ui    = (const float*)d_in[4];
    const float* Wf    = (const float*)d_in[5];
    const float* Uf    = (const float*)d_in[6];
    const float* Wo    = (const float*)d_in[7];
    const float* Uo    = (const float*)d_in[8];
    const float* Wg    = (const float*)d_in[9];
    const float* Ug    = (const float*)d_in[10];
    float* out = (float*)d_out;

    setup_k<<<1, 1024>>>(zx, zh, Wi, Ui, Wf, Uf, Wo, Uo, Wg, Ug);
    xproj_k<<<(NCHAIN*T_LEN + 255)/256, 256>>>(input);
    lstm_k<<<NCHAIN, 16>>>();
    reduce_k<<<(T_LEN*BATCH*HDIM + 255)/256, 256>>>(out);
}

// round 13
// speedup vs baseline: 2.7980x; 2.7980x over previous
#include <cuda_runtime.h>
#include <cstdint>

#define T_LEN  16384
#define BATCH  10
#define DDIM   3
#define HDIM   4
#define NITER  10
#define NCHAIN (NITER*BATCH)   // 100
#define NGATE  16

// ---------------- device scratch (static: no allocation allowed) ----------------
// NEW layout (u-major, gate-fastest): k = u*4 + gate, gates 0=i 1=f 2=o 3=g
__device__ float g_W2[NITER*DDIM*NGATE];                // [it][d][u][gate], zx & 0.5 folded
__device__ float g_U2[NITER*HDIM*NGATE];                // [it][j][u][gate], zh & 0.5 folded
__device__ float g_xproj[(size_t)NCHAIN*T_LEN*NGATE];   // 104.9 MB  [chain][t][u][gate]
__device__ float g_scratch[(size_t)T_LEN*NCHAIN*16];    // 104.9 MB  [t][chain][u][4] = (o,h,c,tc)

// ---------------- helpers ----------------
__device__ __forceinline__ float tanh_ap(float x) {
    float y; asm("tanh.approx.f32 %0, %1;" : "=f"(y) : "f"(x)); return y;
}

// ---------------- 1) fold masks/scales into W2, U2 ----------------
// Scale 0.5 for i,f,o (sigmoid(a) = 0.5*tanh(a/2)+0.5), 1.0 for g.
__global__ void setup_k(const float* __restrict__ zx, const float* __restrict__ zh,
                        const float* __restrict__ Wi, const float* __restrict__ Ui,
                        const float* __restrict__ Wf, const float* __restrict__ Uf,
                        const float* __restrict__ Wo, const float* __restrict__ Uo,
                        const float* __restrict__ Wg, const float* __restrict__ Ug) {
    int tid = blockIdx.x * blockDim.x + threadIdx.x;
    if (tid < NITER*DDIM*NGATE) {                  // W2[it][d][u][gate]
        int k = tid % NGATE, d = (tid / NGATE) % DDIM, it = tid / (NGATE*DDIM);
        int gate = k & 3, u = k >> 2;
        const float* W = (gate == 0) ? Wi : (gate == 1) ? Wf : (gate == 2) ? Wo : Wg;
        float s = (gate < 3) ? 0.5f : 1.0f;
        g_W2[tid] = zx[it*DDIM + d] * W[d*HDIM + u] * s;
    }
    if (tid < NITER*HDIM*NGATE) {                  // U2[it][j][u][gate]
        int k = tid % NGATE, j = (tid / NGATE) % HDIM, it = tid / (NGATE*HDIM);
        int gate = k & 3, u = k >> 2;
        const float* U = (gate == 0) ? Ui : (gate == 1) ? Uf : (gate == 2) ? Uo : Ug;
        float s = (gate < 3) ? 0.5f : 1.0f;
        g_U2[tid] = zh[it*HDIM + j] * U[j*HDIM + u] * s;
    }
}

// ---------------- 2) precompute xproj[chain][t][u][gate] ----------------
// (code identical to before: the layout change lives entirely in g_W2's index)
__global__ void __launch_bounds__(256) xproj_k(const float* __restrict__ x) {
    int tid = blockIdx.x * blockDim.x + threadIdx.x;     // chain-major, t fastest
    int t = tid % T_LEN;
    int chain = tid / T_LEN;
    if (chain >= NCHAIN) return;
    int it = chain / BATCH, b = chain % BATCH;
    const float* xr = x + ((size_t)t*BATCH + b)*DDIM;
    float x0 = xr[0], x1 = xr[1], x2 = xr[2];
    const float* W = g_W2 + it*DDIM*NGATE;
    float v[NGATE];
#pragma unroll
    for (int k = 0; k < NGATE; k++)
        v[k] = x0*W[k] + x1*W[NGATE + k] + x2*W[2*NGATE + k];
    float4* out = (float4*)(g_xproj + ((size_t)chain*T_LEN + t)*NGATE);
    out[0] = make_float4(v[0],  v[1],  v[2],  v[3]);
    out[1] = make_float4(v[4],  v[5],  v[6],  v[7]);
    out[2] = make_float4(v[8],  v[9],  v[10], v[11]);
    out[3] = make_float4(v[12], v[13], v[14], v[15]);
}

// ---------------- 3) serial recurrence: 4 lanes per chain, lane u owns unit u ----------
// Each lane computes ALL FOUR of its unit's gate pre-activations (one LDG.128
// delivers a_i,a_f,a_o,a_g), so the gate-gather shfl round of the previous
// design is gone: only the h-broadcast round (1x ~26 cyc) remains per step.
// Convergent STG.128 per lane to distinct addresses (no branch, no hotspot).
__global__ void __launch_bounds__(4, 1) lstm_k() {
    const int u     = threadIdx.x;      // 0..3 = unit
    const int chain = blockIdx.x;
    const unsigned FULL = 0xFu;

    // per-lane recurrent weights: U2[it][j][u][gate] for j=0..3 (folded)
    const float* Ub = g_U2 + (chain / BATCH)*HDIM*NGATE + u*4;
    const float4 U0 = *(const float4*)(Ub + 0*NGATE);
    const float4 U1 = *(const float4*)(Ub + 1*NGATE);
    const float4 U2v = *(const float4*)(Ub + 2*NGATE);
    const float4 U3 = *(const float4*)(Ub + 3*NGATE);

    const float4* xp  = (const float4*)(g_xproj + (size_t)chain*T_LEN*NGATE) + u;  // stride 4 float4/step
    float4*       stp = (float4*)g_scratch + (size_t)chain*4 + u;                   // stride NCHAIN*4/step

    float h = 0.f, c = 0.f;

    // 8-deep prefetch pipeline: one LDG.128 per lane per step, ~800+ cyc lookahead
    float4 xbuf[8];
#pragma unroll
    for (int p = 0; p < 8; p++) xbuf[p] = xp[(size_t)p*4];

    for (int t = 0; t < T_LEN; t += 8) {
#pragma unroll
        for (int p = 0; p < 8; p++) {
            float4 xv = xbuf[p];
            int nf = t + 8 + p; nf = (nf < T_LEN) ? nf : (T_LEN - 1);
            xbuf[p] = xp[(size_t)nf*4];                  // issue-only cost, hidden in stalls

            // single shfl round: broadcast h0..h3 (lane j owns h_j)
            float h0 = __shfl_sync(FULL, h, 0, 4);
            float h1 = __shfl_sync(FULL, h, 1, 4);
            float h2 = __shfl_sync(FULL, h, 2, 4);
            float h3 = __shfl_sync(FULL, h, 3, 4);

            // four gate pre-acts for THIS unit (balanced trees, depth ~12 cyc)
            float ai = fmaf(h1, U1.x, fmaf(h0, U0.x, xv.x)) + fmaf(h3, U3.x, h2*U2v.x);
            float af = fmaf(h1, U1.y, fmaf(h0, U0.y, xv.y)) + fmaf(h3, U3.y, h2*U2v.y);
            float ao = fmaf(h1, U1.z, fmaf(h0, U0.z, xv.z)) + fmaf(h3, U3.z, h2*U2v.z);
            float ag = fmaf(h1, U1.w, fmaf(h0, U0.w, xv.w)) + fmaf(h3, U3.w, h2*U2v.w);

            // MUFU order: g,i first (needed earliest for i*g), then f, then o
            float tg_ = tanh_ap(ag);
            float ti_ = tanh_ap(ai);
            float tf_ = tanh_ap(af);
            float to_ = tanh_ap(ao);

            // sigmoid(x) = 0.5*tanh(x/2)+0.5 (the /2 is folded into W2/U2)
            float iv = fmaf(ti_, 0.5f, 0.5f);
            float fv = fmaf(tf_, 0.5f, 0.5f);
            float ov = fmaf(to_, 0.5f, 0.5f);

            c = fmaf(fv, c, iv*tg_);
            float tc = tanh_ap(c);
            h = ov*tc;

            // convergent STG.128, distinct per (chain,u) addresses, 64B/warp
            stp[(size_t)(t + p)*(NCHAIN*4)] = make_float4(ov, h, c, tc);
        }
    }
}

// ---------------- 4) deterministic mean over the 10 MC iterations ----------------
__global__ void __launch_bounds__(256) reduce_k(float* __restrict__ out) {
    int tid = blockIdx.x * blockDim.x + threadIdx.x;
    if (tid >= T_LEN*BATCH*HDIM) return;
    int u = tid & 3;
    int b = (tid >> 2) % BATCH;
    int t = tid / (BATCH*HDIM);
    const float4* base = (const float4*)g_scratch + (size_t)t*NCHAIN*4 + b*4 + u;
    float so = 0.f, sh = 0.f, scc = 0.f;
#pragma unroll
    for (int it = 0; it < NITER; it++) {
        float4 v = base[(size_t)it*BATCH*4];             // chain = it*BATCH + b
        so += v.x; sh += v.y; scc += v.z;
    }
    size_t o_idx = ((size_t)t*BATCH + b)*HDIM + u;
    const size_t TEN = (size_t)T_LEN*BATCH*HDIM;
    out[o_idx]         = 0.1f*so;
    out[TEN + o_idx]   = 0.1f*sh;
    out[2*TEN + o_idx] = 0.1f*scc;
}

// ---------------- launch ----------------
extern "C" void kernel_launch(void* const* d_in, const int* in_sizes, int n_in,
                              void* d_out, int out_size) {
    const float* input = (const float*)d_in[0];
    const float* zx    = (const float*)d_in[1];
    const float* zh    = (const float*)d_in[2];
    const float* Wi    = (const float*)d_in[3];
    const float* Ui    = (const float*)d_in[4];
    const float* Wf    = (const float*)d_in[5];
    const float* Uf    = (const float*)d_in[6];
    const float* Wo    = (const float*)d_in[7];
    const float* Uo    = (const float*)d_in[8];
    const float* Wg    = (const float*)d_in[9];
    const float* Ug    = (const float*)d_in[10];
    float* out = (float*)d_out;

    setup_k<<<1, 1024>>>(zx, zh, Wi, Ui, Wf, Uf, Wo, Uo, Wg, Ug);
    xproj_k<<<(NCHAIN*T_LEN + 255)/256, 256>>>(input);
    lstm_k<<<NCHAIN, 4>>>();
    reduce_k<<<(T_LEN*BATCH*HDIM + 255)/256, 256>>>(out);
}